// round 5
// baseline (speedup 1.0000x reference)
#include <cuda_runtime.h>
#include <math.h>

#define Bc 2
#define Mc 8192
#define Nc (Bc * Mc)
#define KF 16
#define KN 8
#define NB 4096
#define BCAP 64

#define QPB 112                 // queries per block
#define SPLITS 4                // slice-threads per query
#define KTH (QPB * SPLITS)      // 448 threads
#define SLICE (Mc / SPLITS)     // 2048 candidates per thread
#define QBLKS 74                // ceil(8192/112) -> grid = 148 exactly

// ---- scratch (device globals; no allocation allowed) ----
__device__ int    g_knn[(size_t)Nc * KF];
__device__ double g_acc[8];
__device__ int    g_hist[Bc][NB];
__device__ int    g_pref[Bc][NB];
__device__ int    g_members[Bc][NB * BCAP];

// ----- direction-free compare-exchange: a=min, b=max (2 ALU ops, no SEL) -----
__device__ __forceinline__ void ceu(unsigned& a, unsigned& b) {
    unsigned lo = min(a, b);
    b = max(a, b);
    a = lo;
}

// Batcher odd-even mergesort, n=16, ascending (63 CE)
__device__ __forceinline__ void sort16(unsigned k[16]) {
#pragma unroll
    for (int p = 1; p < 16; p <<= 1)
#pragma unroll
        for (int q = p; q >= 1; q >>= 1)
#pragma unroll
            for (int j = q % p; j + q < 16; j += 2 * q)
#pragma unroll
                for (int i = 0; i < q; ++i) {
                    const int lo = i + j, hi = i + j + q;
                    if (hi < 16 && (lo / (2 * p)) == (hi / (2 * p)))
                        ceu(k[lo], k[hi]);
                }
}

// bitonic cleaner: bitonic 16-sequence -> ascending (32 CE)
__device__ __forceinline__ void clean16(unsigned k[16]) {
#pragma unroll
    for (int j = 8; j; j >>= 1)
#pragma unroll
        for (int i = 0; i < 16; ++i)
            if ((i & j) == 0) ceu(k[i], k[i + j]);
}

// load 16 candidates, build keys: d21 (sortable float, top 21 bits) | idx11
__device__ __forceinline__ void batch_keys(const float4* __restrict__ p, int base,
                                           float qx, float qy, float qz,
                                           unsigned bk[16]) {
#pragma unroll
    for (int i = 0; i < 16; ++i) {
        float4 c = p[i];
        float d = fmaf(qx, c.x, fmaf(qy, c.y, fmaf(qz, c.z, c.w)));
        unsigned u = __float_as_uint(d);
        unsigned t = (unsigned)((int)u >> 31);        // SHF
        unsigned s = u ^ (t | 0x80000000u);           // LOP3
        bk[i] = (s & 0xFFFFF800u) | (unsigned)(base + i);  // LOP3
    }
}

// merge-keep-16: tk (asc) vs bk (asc, reverse-indexed) -> tk asc
__device__ __forceinline__ void merge16(unsigned tk[16], const unsigned bk[16]) {
#pragma unroll
    for (int i = 0; i < 16; ++i) tk[i] = min(tk[i], bk[15 - i]);
    clean16(tk);
}

// ================= kNN: thread-per-query, batch-sort selection =================
extern "C" __global__ void __launch_bounds__(KTH, 1)
knn_kernel(const float* __restrict__ coords) {
    extern __shared__ unsigned char sraw[];
    float4* sh = (float4*)sraw;

    const int tid = threadIdx.x;
    const int cloud = blockIdx.x / QBLKS;
    const int qblk = blockIdx.x % QBLKS;

    const float* cb = coords + (size_t)cloud * Mc * 3;
    for (int i = tid; i < Mc; i += KTH) {
        float x = cb[3 * i], y = cb[3 * i + 1], z = cb[3 * i + 2];
        sh[i] = make_float4(x, y, z, fmaf(x, x, fmaf(y, y, z * z)));
    }
    __syncthreads();

    const int qLocal = tid % QPB;
    const int split = tid / QPB;
    int q = qblk * QPB + qLocal;
    const bool valid = (q < Mc);
    if (!valid) q = Mc - 1;               // pad threads compute garbage, skip write
    const int slbase = split * SLICE;

    const float4 qc = sh[q];
    const float qx = -2.0f * qc.x;
    const float qy = -2.0f * qc.y;
    const float qz = -2.0f * qc.z;

    const float4* ps = sh + slbase;

    // dual independent accumulator chains (ILP); union's top-16 preserved:
    // any global-top-16 element is top-16 within its own chain's stream.
    unsigned tkA[16], tkB[16];
    batch_keys(ps, 0, qx, qy, qz, tkA);
    sort16(tkA);
    batch_keys(ps + 16, 16, qx, qy, qz, tkB);
    sort16(tkB);

#pragma unroll 1
    for (int b = 2; b < SLICE / 16; b += 2) {
        unsigned bk1[16], bk2[16];
        batch_keys(ps + b * 16, b * 16, qx, qy, qz, bk1);
        batch_keys(ps + b * 16 + 16, b * 16 + 16, qx, qy, qz, bk2);
        sort16(bk1);
        sort16(bk2);
        merge16(tkA, bk1);
        merge16(tkB, bk2);
    }
    merge16(tkA, tkB);

    // ---- in-block 4-way merge (exact lexicographic on (d21, gidx)) ----
    __syncthreads();                       // done reading coords
    int* sd = (int*)sraw;                  // [QPB*65]
    int* sg = sd + QPB * 65;               // [QPB*65]
    const int rowbase = qLocal * 65 + split * 16;
#pragma unroll
    for (int t = 0; t < 16; ++t) {
        unsigned key = tkA[t];
        sd[rowbase + t] = (int)(key >> 11);
        sg[rowbase + t] = slbase + (int)(key & 0x7FFu);
    }
    __syncthreads();

    if (split == 0 && valid) {
        const int* ld = sd + qLocal * 65;
        const int* lg = sg + qLocal * 65;
        const int goff = cloud * Mc;
        int p0 = 0, p1 = 0, p2 = 0, p3 = 0;
        int* out = g_knn + ((size_t)goff + q) * KF;
#pragma unroll 1
        for (int r = 0; r < KF; ++r) {
            int d0 = ld[p0];      int g0 = lg[p0];
            int d1 = ld[16 + p1]; int g1 = lg[16 + p1];
            int d2 = ld[32 + p2]; int g2 = lg[32 + p2];
            int d3 = ld[48 + p3]; int g3 = lg[48 + p3];
            int da, ga, la;
            if (d1 < d0 || (d1 == d0 && g1 < g0)) { da = d1; ga = g1; la = 1; }
            else                                  { da = d0; ga = g0; la = 0; }
            int db, gb, lb;
            if (d3 < d2 || (d3 == d2 && g3 < g2)) { db = d3; gb = g3; lb = 3; }
            else                                  { db = d2; gb = g2; lb = 2; }
            int sel, gbest;
            if (db < da || (db == da && gb < ga)) { sel = lb; gbest = gb; }
            else                                  { sel = la; gbest = ga; }
            out[r] = goff + gbest;
            if      (sel == 0) ++p0;
            else if (sel == 1) ++p1;
            else if (sel == 2) ++p2;
            else               ++p3;
        }
    }
}

// ================= rank bucketing (exact, replaces sort) =================
__global__ void zero_kernel() {
    const int t = blockIdx.x * blockDim.x + threadIdx.x;
    if (t < 8) g_acc[t] = 0.0;
    for (int i = t; i < Bc * NB; i += gridDim.x * blockDim.x)
        ((int*)g_hist)[i] = 0;
}

__global__ void rank_build_kernel(const float* __restrict__ scores) {
    const int i = blockIdx.x * blockDim.x + threadIdx.x;
    if (i >= Nc) return;
    const int cloud = i >> 13;
    const int local = i & (Mc - 1);
    const float s = scores[i];
    int b = (int)(s * (float)NB);
    b = b < 0 ? 0 : (b > NB - 1 ? NB - 1 : b);
    const int slot = atomicAdd(&g_hist[cloud][b], 1);
    if (slot < BCAP) g_members[cloud][b * BCAP + slot] = local;
}

__global__ void prefix_kernel() {
    __shared__ int sc[1024];
    const int cloud = blockIdx.x;
    const int t = threadIdx.x;
    const int base = t * 4;
    int h0 = g_hist[cloud][base + 0];
    int h1 = g_hist[cloud][base + 1];
    int h2 = g_hist[cloud][base + 2];
    int h3 = g_hist[cloud][base + 3];
    int sum = h0 + h1 + h2 + h3;
    sc[t] = sum;
    __syncthreads();
    for (int off = 1; off < 1024; off <<= 1) {
        int v = (t >= off) ? sc[t - off] : 0;
        __syncthreads();
        sc[t] += v;
        __syncthreads();
    }
    int excl = sc[t] - sum;
    g_pref[cloud][base + 0] = excl; excl += h0;
    g_pref[cloud][base + 1] = excl; excl += h1;
    g_pref[cloud][base + 2] = excl; excl += h2;
    g_pref[cloud][base + 3] = excl;
}

// ================= per-point losses (+ rank dist loss) =================
__global__ void loss_points_kernel(const float* __restrict__ scores,
                                   const float* __restrict__ coords) {
    const int i = blockIdx.x * blockDim.x + threadIdx.x;
    double acc[6] = {0, 0, 0, 0, 0, 0};

    {
        const float si = scores[i];
        const float xi = coords[3 * i], yi = coords[3 * i + 1], zi = coords[3 * i + 2];
        float nsum = 0.0f;
        const int* nb = g_knn + (size_t)i * KF;
#pragma unroll
        for (int r = 0; r < KF; ++r) {
            const int n = nb[r];
            const float sn = scores[n];
            const float sd = fabsf(si - sn);
            const float x = (1.0f - sd) * 2.0f;
            const float sig = 1.0f / (1.0f + expf(-x));
            if (r < KN) {
                const float dx = xi - coords[3 * n];
                const float dy = yi - coords[3 * n + 1];
                const float dz = zi - coords[3 * n + 2];
                const float dist = sqrtf(dx * dx + dy * dy + dz * dz);
                const float w = expf(-dist * 10.0f);
                acc[0] += (double)(w * sd * sd);
                acc[1] += (double)w;
                acc[2] += (double)logf(sig + 1e-8f);
                nsum += sn;
            } else {
                acc[3] += (double)logf(1.0f - sig + 1e-8f);
            }
        }
        const float dm = si - nsum * 0.125f;
        acc[4] = (double)(dm * dm);

        const int cloud = i >> 13;
        const int local = i & (Mc - 1);
        int b = (int)(si * (float)NB);
        b = b < 0 ? 0 : (b > NB - 1 ? NB - 1 : b);
        int cnt = g_hist[cloud][b];
        cnt = cnt > BCAP ? BCAP : cnt;
        int r = 0;
        const int* mem = &g_members[cloud][b * BCAP];
        for (int k = 0; k < cnt; ++k) {
            const int m = mem[k];
            const float sm = scores[(cloud << 13) + m];
            r += (sm < si) || (sm == si && m < local);
        }
        const int rank = g_pref[cloud][b] + r;
        const float df = si - (float)rank * (1.0f / (float)(Mc - 1));
        acc[5] = (double)(df * df);
    }

    const int lane = threadIdx.x & 31;
    const int wid = threadIdx.x >> 5;
#pragma unroll
    for (int k = 0; k < 6; ++k)
#pragma unroll
        for (int o = 16; o; o >>= 1)
            acc[k] += __shfl_down_sync(0xffffffffu, acc[k], o);

    __shared__ double red[8][6];
    if (lane == 0)
#pragma unroll
        for (int k = 0; k < 6; ++k) red[wid][k] = acc[k];
    __syncthreads();
    if (wid == 0 && lane < 6) {
        double s = 0.0;
#pragma unroll
        for (int w = 0; w < 8; ++w) s += red[w][lane];
        atomicAdd(&g_acc[lane], s);
    }
}

// ================= finalize =================
__global__ void finalize_kernel(float* out) {
    const double l_loc = g_acc[0] / fmax(g_acc[1], 1e-8);
    const double l_pos = -g_acc[2] / (double)((size_t)Nc * KN);
    const double l_neg = -g_acc[3] / (double)((size_t)Nc * KN);
    const double l_con = l_pos + l_neg;
    const double l_smooth = g_acc[4] / (double)Nc;
    const double l_dist = g_acc[5] / (double)Nc;
    out[0] = (float)(1.0 * l_loc + 0.5 * l_con + 0.3 * l_dist + 0.2 * l_smooth);
}

extern "C" void kernel_launch(void* const* d_in, const int* in_sizes, int n_in,
                              void* d_out, int out_size) {
    const float* scores = (const float*)d_in[0];
    const float* coords = (const float*)d_in[1];
    (void)in_sizes; (void)n_in; (void)out_size;

    cudaFuncSetAttribute(knn_kernel,
                         cudaFuncAttributeMaxDynamicSharedMemorySize,
                         Mc * (int)sizeof(float4));

    zero_kernel<<<16, 1024>>>();
    rank_build_kernel<<<Nc / 256, 256>>>(scores);
    prefix_kernel<<<Bc, 1024>>>();
    knn_kernel<<<Bc * QBLKS, KTH, Mc * sizeof(float4)>>>(coords);
    loss_points_kernel<<<Nc / 256, 256>>>(scores, coords);
    finalize_kernel<<<1, 1>>>((float*)d_out);
}

// round 6
// speedup vs baseline: 1.0808x; 1.0808x over previous
#include <cuda_runtime.h>
#include <math.h>

#define Bc 2
#define Mc 8192
#define Nc (Bc * Mc)
#define KF 16
#define KN 8
#define NB 4096
#define BCAP 64

#define QPB 112                 // queries per block
#define SPLITS 4                // slice-threads per query
#define KTH (QPB * SPLITS)      // 448 threads
#define SLICE (Mc / SPLITS)     // 2048 candidates per thread
#define QBLKS 74                // ceil(8192/112) -> grid = 148 exactly

// ---- scratch (device globals; no allocation allowed) ----
__device__ int    g_knn[(size_t)Nc * KF];
__device__ double g_acc[8];
__device__ int    g_hist[Bc][NB];
__device__ int    g_pref[Bc][NB];
__device__ int    g_members[Bc][NB * BCAP];

// ----- direction-free compare-exchange: a=min, b=max (2 ALU ops, no SEL) -----
__device__ __forceinline__ void ceu(unsigned& a, unsigned& b) {
    unsigned lo = min(a, b);
    b = max(a, b);
    a = lo;
}

// Batcher odd-even mergesort, n=16, ascending (63 CE)
__device__ __forceinline__ void sort16(unsigned k[16]) {
#pragma unroll
    for (int p = 1; p < 16; p <<= 1)
#pragma unroll
        for (int q = p; q >= 1; q >>= 1)
#pragma unroll
            for (int j = q % p; j + q < 16; j += 2 * q)
#pragma unroll
                for (int i = 0; i < q; ++i) {
                    const int lo = i + j, hi = i + j + q;
                    if (hi < 16 && (lo / (2 * p)) == (hi / (2 * p)))
                        ceu(k[lo], k[hi]);
                }
}

// bitonic cleaner: bitonic 16-sequence -> ascending (32 CE)
__device__ __forceinline__ void clean16(unsigned k[16]) {
#pragma unroll
    for (int j = 8; j; j >>= 1)
#pragma unroll
        for (int i = 0; i < 16; ++i)
            if ((i & j) == 0) ceu(k[i], k[i + j]);
}

// load 16 candidates, build keys: d21 (sortable float, top 21 bits) | idx11
__device__ __forceinline__ void batch_keys(const float4* __restrict__ p, int base,
                                           float qx, float qy, float qz,
                                           unsigned bk[16]) {
#pragma unroll
    for (int i = 0; i < 16; ++i) {
        float4 c = p[i];
        float d = fmaf(qx, c.x, fmaf(qy, c.y, fmaf(qz, c.z, c.w)));
        unsigned u = __float_as_uint(d);
        unsigned t = (unsigned)((int)u >> 31);              // SHF
        unsigned s = u ^ (t | 0x80000000u);                 // LOP3
        bk[i] = (s & 0xFFFFF800u) | (unsigned)(base + i);   // LOP3
    }
}

// ================= kNN: thread-per-query, batch-sort selection =================
extern "C" __global__ void __launch_bounds__(KTH, 1)
knn_kernel(const float* __restrict__ coords) {
    extern __shared__ unsigned char sraw[];
    float4* sh = (float4*)sraw;

    const int tid = threadIdx.x;
    const int cloud = blockIdx.x / QBLKS;
    const int qblk = blockIdx.x % QBLKS;

    const float* cb = coords + (size_t)cloud * Mc * 3;
    for (int i = tid; i < Mc; i += KTH) {
        float x = cb[3 * i], y = cb[3 * i + 1], z = cb[3 * i + 2];
        sh[i] = make_float4(x, y, z, fmaf(x, x, fmaf(y, y, z * z)));
    }
    __syncthreads();

    const int qLocal = tid % QPB;
    const int split = tid / QPB;
    int q = qblk * QPB + qLocal;
    const bool valid = (q < Mc);
    if (!valid) q = Mc - 1;               // pad threads compute garbage, skip write
    const int slbase = split * SLICE;

    const float4 qc = sh[q];
    const float qx = -2.0f * qc.x;
    const float qy = -2.0f * qc.y;
    const float qz = -2.0f * qc.z;

    const float4* ps = sh + slbase;

    // single running top-16 chain (R4-proven register footprint)
    unsigned tk[16];
    batch_keys(ps, 0, qx, qy, qz, tk);
    sort16(tk);

#pragma unroll 1
    for (int b = 1; b < SLICE / 16; ++b) {
        unsigned bk[16];
        batch_keys(ps + b * 16, b * 16, qx, qy, qz, bk);
        sort16(bk);
        // keep 16 smallest of (tk ∪ bk): elementwise min vs reversed, clean
#pragma unroll
        for (int i = 0; i < 16; ++i) tk[i] = min(tk[i], bk[15 - i]);
        clean16(tk);
    }

    // ---- in-block 4-way merge (exact lexicographic on (d21, gidx)) ----
    __syncthreads();                       // done reading coords
    int* sd = (int*)sraw;                  // [QPB*65]
    int* sg = sd + QPB * 65;               // [QPB*65]
    const int rowbase = qLocal * 65 + split * 16;
#pragma unroll
    for (int t = 0; t < 16; ++t) {
        unsigned key = tk[t];
        sd[rowbase + t] = (int)(key >> 11);
        sg[rowbase + t] = slbase + (int)(key & 0x7FFu);
    }
    __syncthreads();

    if (split == 0 && valid) {
        const int* ld = sd + qLocal * 65;
        const int* lg = sg + qLocal * 65;
        const int goff = cloud * Mc;
        int p0 = 0, p1 = 0, p2 = 0, p3 = 0;
        int* out = g_knn + ((size_t)goff + q) * KF;
#pragma unroll 1
        for (int r = 0; r < KF; ++r) {
            int d0 = ld[p0];      int g0 = lg[p0];
            int d1 = ld[16 + p1]; int g1 = lg[16 + p1];
            int d2 = ld[32 + p2]; int g2 = lg[32 + p2];
            int d3 = ld[48 + p3]; int g3 = lg[48 + p3];
            int da, ga, la;
            if (d1 < d0 || (d1 == d0 && g1 < g0)) { da = d1; ga = g1; la = 1; }
            else                                  { da = d0; ga = g0; la = 0; }
            int db, gb, lb;
            if (d3 < d2 || (d3 == d2 && g3 < g2)) { db = d3; gb = g3; lb = 3; }
            else                                  { db = d2; gb = g2; lb = 2; }
            int sel, gbest;
            if (db < da || (db == da && gb < ga)) { sel = lb; gbest = gb; }
            else                                  { sel = la; gbest = ga; }
            out[r] = goff + gbest;
            if      (sel == 0) ++p0;
            else if (sel == 1) ++p1;
            else if (sel == 2) ++p2;
            else               ++p3;
        }
    }
}

// ================= rank bucketing (exact, replaces sort) =================
__global__ void zero_kernel() {
    const int t = blockIdx.x * blockDim.x + threadIdx.x;
    if (t < 8) g_acc[t] = 0.0;
    for (int i = t; i < Bc * NB; i += gridDim.x * blockDim.x)
        ((int*)g_hist)[i] = 0;
}

__global__ void rank_build_kernel(const float* __restrict__ scores) {
    const int i = blockIdx.x * blockDim.x + threadIdx.x;
    if (i >= Nc) return;
    const int cloud = i >> 13;
    const int local = i & (Mc - 1);
    const float s = scores[i];
    int b = (int)(s * (float)NB);
    b = b < 0 ? 0 : (b > NB - 1 ? NB - 1 : b);
    const int slot = atomicAdd(&g_hist[cloud][b], 1);
    if (slot < BCAP) g_members[cloud][b * BCAP + slot] = local;
}

__global__ void prefix_kernel() {
    __shared__ int sc[1024];
    const int cloud = blockIdx.x;
    const int t = threadIdx.x;
    const int base = t * 4;
    int h0 = g_hist[cloud][base + 0];
    int h1 = g_hist[cloud][base + 1];
    int h2 = g_hist[cloud][base + 2];
    int h3 = g_hist[cloud][base + 3];
    int sum = h0 + h1 + h2 + h3;
    sc[t] = sum;
    __syncthreads();
    for (int off = 1; off < 1024; off <<= 1) {
        int v = (t >= off) ? sc[t - off] : 0;
        __syncthreads();
        sc[t] += v;
        __syncthreads();
    }
    int excl = sc[t] - sum;
    g_pref[cloud][base + 0] = excl; excl += h0;
    g_pref[cloud][base + 1] = excl; excl += h1;
    g_pref[cloud][base + 2] = excl; excl += h2;
    g_pref[cloud][base + 3] = excl;
}

// ================= per-point losses (+ rank dist loss) =================
__global__ void loss_points_kernel(const float* __restrict__ scores,
                                   const float* __restrict__ coords) {
    const int i = blockIdx.x * blockDim.x + threadIdx.x;
    double acc[6] = {0, 0, 0, 0, 0, 0};

    {
        const float si = scores[i];
        const float xi = coords[3 * i], yi = coords[3 * i + 1], zi = coords[3 * i + 2];
        float nsum = 0.0f;
        const int* nb = g_knn + (size_t)i * KF;
#pragma unroll
        for (int r = 0; r < KF; ++r) {
            const int n = nb[r];
            const float sn = scores[n];
            const float sd = fabsf(si - sn);
            const float x = (1.0f - sd) * 2.0f;
            const float sig = 1.0f / (1.0f + expf(-x));
            if (r < KN) {
                const float dx = xi - coords[3 * n];
                const float dy = yi - coords[3 * n + 1];
                const float dz = zi - coords[3 * n + 2];
                const float dist = sqrtf(dx * dx + dy * dy + dz * dz);
                const float w = expf(-dist * 10.0f);
                acc[0] += (double)(w * sd * sd);
                acc[1] += (double)w;
                acc[2] += (double)logf(sig + 1e-8f);
                nsum += sn;
            } else {
                acc[3] += (double)logf(1.0f - sig + 1e-8f);
            }
        }
        const float dm = si - nsum * 0.125f;
        acc[4] = (double)(dm * dm);

        const int cloud = i >> 13;
        const int local = i & (Mc - 1);
        int b = (int)(si * (float)NB);
        b = b < 0 ? 0 : (b > NB - 1 ? NB - 1 : b);
        int cnt = g_hist[cloud][b];
        cnt = cnt > BCAP ? BCAP : cnt;
        int r = 0;
        const int* mem = &g_members[cloud][b * BCAP];
        for (int k = 0; k < cnt; ++k) {
            const int m = mem[k];
            const float sm = scores[(cloud << 13) + m];
            r += (sm < si) || (sm == si && m < local);
        }
        const int rank = g_pref[cloud][b] + r;
        const float df = si - (float)rank * (1.0f / (float)(Mc - 1));
        acc[5] = (double)(df * df);
    }

    const int lane = threadIdx.x & 31;
    const int wid = threadIdx.x >> 5;
#pragma unroll
    for (int k = 0; k < 6; ++k)
#pragma unroll
        for (int o = 16; o; o >>= 1)
            acc[k] += __shfl_down_sync(0xffffffffu, acc[k], o);

    __shared__ double red[8][6];
    if (lane == 0)
#pragma unroll
        for (int k = 0; k < 6; ++k) red[wid][k] = acc[k];
    __syncthreads();
    if (wid == 0 && lane < 6) {
        double s = 0.0;
#pragma unroll
        for (int w = 0; w < 8; ++w) s += red[w][lane];
        atomicAdd(&g_acc[lane], s);
    }
}

// ================= finalize =================
__global__ void finalize_kernel(float* out) {
    const double l_loc = g_acc[0] / fmax(g_acc[1], 1e-8);
    const double l_pos = -g_acc[2] / (double)((size_t)Nc * KN);
    const double l_neg = -g_acc[3] / (double)((size_t)Nc * KN);
    const double l_con = l_pos + l_neg;
    const double l_smooth = g_acc[4] / (double)Nc;
    const double l_dist = g_acc[5] / (double)Nc;
    out[0] = (float)(1.0 * l_loc + 0.5 * l_con + 0.3 * l_dist + 0.2 * l_smooth);
}

extern "C" void kernel_launch(void* const* d_in, const int* in_sizes, int n_in,
                              void* d_out, int out_size) {
    const float* scores = (const float*)d_in[0];
    const float* coords = (const float*)d_in[1];
    (void)in_sizes; (void)n_in; (void)out_size;

    cudaFuncSetAttribute(knn_kernel,
                         cudaFuncAttributeMaxDynamicSharedMemorySize,
                         Mc * (int)sizeof(float4));

    zero_kernel<<<16, 1024>>>();
    rank_build_kernel<<<Nc / 256, 256>>>(scores);
    prefix_kernel<<<Bc, 1024>>>();
    knn_kernel<<<Bc * QBLKS, KTH, Mc * sizeof(float4)>>>(coords);
    loss_points_kernel<<<Nc / 256, 256>>>(scores, coords);
    finalize_kernel<<<1, 1>>>((float*)d_out);
}

// round 7
// speedup vs baseline: 2.3318x; 2.1576x over previous
#include <cuda_runtime.h>
#include <math.h>

#define Bc 2
#define Mc 8192
#define Nc (Bc * Mc)
#define KF 16
#define KN 8
#define NB 4096
#define BCAP 64

#define QPB 64                  // queries per block
#define SPLITS 8                // slice-threads per query
#define KTH (QPB * SPLITS)      // 512 threads
#define QBLKS (Mc / QPB)        // 128 per cloud; grid = 256
#define PASS_CANDS 4096         // candidates staged per pass (64KB)
#define TSLICE 1024             // candidates per thread total (2 passes x 512)

// ---- scratch (device globals; no allocation allowed) ----
__device__ int    g_knn[(size_t)Nc * KF];
__device__ double g_acc[8];
__device__ int    g_hist[Bc][NB];
__device__ int    g_pref[Bc][NB];
__device__ int    g_members[Bc][NB * BCAP];

// ----- compare-exchange, compile-time direction (folds to 2 min/max) -----
__device__ __forceinline__ void ce(unsigned& a, unsigned& b, bool up) {
    unsigned lo = min(a, b), hi = max(a, b);
    a = up ? lo : hi;
    b = up ? hi : lo;
}

// bitonic sort 16 keys ascending (R4-proven register-clean form; 80 CE)
__device__ __forceinline__ void sort16(unsigned k[16]) {
#pragma unroll
    for (int kk = 2; kk <= 16; kk <<= 1)
#pragma unroll
        for (int j = kk >> 1; j; j >>= 1)
#pragma unroll
            for (int i = 0; i < 16; ++i) {
                int l = i ^ j;
                if (l > i) ce(k[i], k[l], (i & kk) == 0);
            }
}

// clean a bitonic 16-sequence -> ascending (32 CE)
__device__ __forceinline__ void clean16(unsigned k[16]) {
#pragma unroll
    for (int j = 8; j; j >>= 1)
#pragma unroll
        for (int i = 0; i < 16; ++i) {
            int l = i ^ j;
            if (l > i) ce(k[i], k[l], true);
        }
}

// ================= kNN =================
// key = (float_bits(d) & 0x7FFFF800) | local_c(11 bits);  d = |c|^2-2q.c+|q|^2 >= -eps
// sign-clear maps the -eps boundary (self distance) to tiny positive: order-safe.
extern "C" __global__ void __launch_bounds__(KTH, 2)
knn_kernel(const float* __restrict__ coords) {
    extern __shared__ unsigned char sraw[];
    float4* sh = (float4*)sraw;

    const int tid = threadIdx.x;
    const int cloud = blockIdx.x >> 7;
    const int qblk = blockIdx.x & 127;
    const int qLocal = tid & (QPB - 1);
    const int split = tid >> 6;            // warp-uniform (64 threads per split)

    const float* cb = coords + (size_t)cloud * Mc * 3;
    const int q = qblk * QPB + qLocal;

    // query from global (staging window may not contain q)
    const float qx = cb[3 * q], qy = cb[3 * q + 1], qz = cb[3 * q + 2];
    const float qw = fmaf(qx, qx, fmaf(qy, qy, qz * qz));
    const float ax = -2.0f * qx, ay = -2.0f * qy, az = -2.0f * qz;

    unsigned tk[16];
#pragma unroll
    for (int t = 0; t < 16; ++t) tk[t] = 0xFFFFFFFFu;

#pragma unroll 1
    for (int pass = 0; pass < 2; ++pass) {
        __syncthreads();                         // previous consumers done
        const int wbase = pass * PASS_CANDS;
        for (int i = tid; i < PASS_CANDS; i += KTH) {
            const int jg = wbase + i;
            float x = cb[3 * jg], y = cb[3 * jg + 1], z = cb[3 * jg + 2];
            sh[i] = make_float4(x, y, z, fmaf(x, x, fmaf(y, y, z * z)));
        }
        __syncthreads();

        const float4* ps = sh + (split << 9);    // this thread's 512-slice
        const int cbase = pass << 9;             // local c base
#pragma unroll 1
        for (int b = 0; b < 512 / 16; ++b) {
            unsigned bk[16];
            const float4* p = ps + b * 16;
#pragma unroll
            for (int i = 0; i < 16; ++i) {
                float4 c = p[i];
                float d = fmaf(ax, c.x, fmaf(ay, c.y, fmaf(az, c.z, c.w + qw)));
                bk[i] = (__float_as_uint(d) & 0x7FFFF800u)
                      | (unsigned)(cbase + b * 16 + i);
            }
            sort16(bk);
#pragma unroll
            for (int i = 0; i < 16; ++i) tk[i] = min(tk[i], bk[15 - i]);
            clean16(tk);
        }
    }

    // ---- exact 8-way merge on (d21, global idx) via 3 pairwise rounds ----
    __syncthreads();
    int2* bufA = (int2*)sraw;                    // [QPB][136]: 8 segs x16 (+pad)
    int2* bufB = bufA + QPB * 136;               // [QPB][68] : 4 segs x16 (+pad)

#pragma unroll
    for (int t = 0; t < 16; ++t) {
        unsigned key = tk[t];
        int c = (int)(key & 0x7FFu);
        int g = ((c >> 9) << 12) + (split << 9) + (c & 511);
        bufA[qLocal * 136 + split * 16 + t] = make_int2((int)(key >> 11), g);
    }
    __syncthreads();

    // serial 2-way merge of two sorted 16-lists -> 16 smallest
#define MERGE2(SRC, OFFA, OFFB, DSTSTMT)                                      \
    {                                                                         \
        int ii = 0, jj = 0;                                                   \
        _Pragma("unroll 1")                                                   \
        for (int r = 0; r < 16; ++r) {                                        \
            int2 a = (SRC)[(OFFA) + min(ii, 15)];                             \
            int2 b = (SRC)[(OFFB) + min(jj, 15)];                             \
            bool takeA = (jj >= 16) ||                                        \
                ((ii < 16) && (a.x < b.x || (a.x == b.x && a.y < b.y)));      \
            int2 o = takeA ? a : b;                                           \
            ii += takeA; jj += !takeA;                                        \
            DSTSTMT;                                                          \
        }                                                                     \
    }

    if (split < 4) {   // round 1: 8 -> 4
        const int ra = qLocal * 136 + split * 32;
        int2* dst = bufB + qLocal * 68 + split * 16;
        MERGE2(bufA, ra, ra + 16, dst[r] = o);
    }
    __syncthreads();
    if (split < 2) {   // round 2: 4 -> 2 (write into bufA front, already consumed)
        const int ra = qLocal * 68 + split * 32;
        int2* dst = bufA + qLocal * 136 + split * 16;
        MERGE2(bufB, ra, ra + 16, dst[r] = o);
    }
    __syncthreads();
    if (split == 0) {  // round 3: 2 -> 1, write result
        const int goff = cloud * Mc;
        int* out = g_knn + ((size_t)goff + q) * KF;
        const int ra = qLocal * 136;
        MERGE2(bufA, ra, ra + 16, out[r] = goff + o.y);
    }
}

// ================= rank bucketing (exact, replaces sort) =================
__global__ void zero_kernel() {
    const int t = blockIdx.x * blockDim.x + threadIdx.x;
    if (t < 8) g_acc[t] = 0.0;
    for (int i = t; i < Bc * NB; i += gridDim.x * blockDim.x)
        ((int*)g_hist)[i] = 0;
}

__global__ void rank_build_kernel(const float* __restrict__ scores) {
    const int i = blockIdx.x * blockDim.x + threadIdx.x;
    if (i >= Nc) return;
    const int cloud = i >> 13;
    const int local = i & (Mc - 1);
    const float s = scores[i];
    int b = (int)(s * (float)NB);
    b = b < 0 ? 0 : (b > NB - 1 ? NB - 1 : b);
    const int slot = atomicAdd(&g_hist[cloud][b], 1);
    if (slot < BCAP) g_members[cloud][b * BCAP + slot] = local;
}

__global__ void prefix_kernel() {
    __shared__ int sc[1024];
    const int cloud = blockIdx.x;
    const int t = threadIdx.x;
    const int base = t * 4;
    int h0 = g_hist[cloud][base + 0];
    int h1 = g_hist[cloud][base + 1];
    int h2 = g_hist[cloud][base + 2];
    int h3 = g_hist[cloud][base + 3];
    int sum = h0 + h1 + h2 + h3;
    sc[t] = sum;
    __syncthreads();
    for (int off = 1; off < 1024; off <<= 1) {
        int v = (t >= off) ? sc[t - off] : 0;
        __syncthreads();
        sc[t] += v;
        __syncthreads();
    }
    int excl = sc[t] - sum;
    g_pref[cloud][base + 0] = excl; excl += h0;
    g_pref[cloud][base + 1] = excl; excl += h1;
    g_pref[cloud][base + 2] = excl; excl += h2;
    g_pref[cloud][base + 3] = excl;
}

// ================= per-point losses (+ rank dist loss) =================
__global__ void loss_points_kernel(const float* __restrict__ scores,
                                   const float* __restrict__ coords) {
    const int i = blockIdx.x * blockDim.x + threadIdx.x;
    double acc[6] = {0, 0, 0, 0, 0, 0};

    {
        const float si = scores[i];
        const float xi = coords[3 * i], yi = coords[3 * i + 1], zi = coords[3 * i + 2];
        float nsum = 0.0f;
        const int* nb = g_knn + (size_t)i * KF;
#pragma unroll
        for (int r = 0; r < KF; ++r) {
            const int n = nb[r];
            const float sn = scores[n];
            const float sd = fabsf(si - sn);
            const float x = (1.0f - sd) * 2.0f;
            const float sig = 1.0f / (1.0f + expf(-x));
            if (r < KN) {
                const float dx = xi - coords[3 * n];
                const float dy = yi - coords[3 * n + 1];
                const float dz = zi - coords[3 * n + 2];
                const float dist = sqrtf(dx * dx + dy * dy + dz * dz);
                const float w = expf(-dist * 10.0f);
                acc[0] += (double)(w * sd * sd);
                acc[1] += (double)w;
                acc[2] += (double)logf(sig + 1e-8f);
                nsum += sn;
            } else {
                acc[3] += (double)logf(1.0f - sig + 1e-8f);
            }
        }
        const float dm = si - nsum * 0.125f;
        acc[4] = (double)(dm * dm);

        const int cloud = i >> 13;
        const int local = i & (Mc - 1);
        int b = (int)(si * (float)NB);
        b = b < 0 ? 0 : (b > NB - 1 ? NB - 1 : b);
        int cnt = g_hist[cloud][b];
        cnt = cnt > BCAP ? BCAP : cnt;
        int r = 0;
        const int* mem = &g_members[cloud][b * BCAP];
        for (int k = 0; k < cnt; ++k) {
            const int m = mem[k];
            const float sm = scores[(cloud << 13) + m];
            r += (sm < si) || (sm == si && m < local);
        }
        const int rank = g_pref[cloud][b] + r;
        const float df = si - (float)rank * (1.0f / (float)(Mc - 1));
        acc[5] = (double)(df * df);
    }

    const int lane = threadIdx.x & 31;
    const int wid = threadIdx.x >> 5;
#pragma unroll
    for (int k = 0; k < 6; ++k)
#pragma unroll
        for (int o = 16; o; o >>= 1)
            acc[k] += __shfl_down_sync(0xffffffffu, acc[k], o);

    __shared__ double red[8][6];
    if (lane == 0)
#pragma unroll
        for (int k = 0; k < 6; ++k) red[wid][k] = acc[k];
    __syncthreads();
    if (wid == 0 && lane < 6) {
        double s = 0.0;
#pragma unroll
        for (int w = 0; w < 8; ++w) s += red[w][lane];
        atomicAdd(&g_acc[lane], s);
    }
}

// ================= finalize =================
__global__ void finalize_kernel(float* out) {
    const double l_loc = g_acc[0] / fmax(g_acc[1], 1e-8);
    const double l_pos = -g_acc[2] / (double)((size_t)Nc * KN);
    const double l_neg = -g_acc[3] / (double)((size_t)Nc * KN);
    const double l_con = l_pos + l_neg;
    const double l_smooth = g_acc[4] / (double)Nc;
    const double l_dist = g_acc[5] / (double)Nc;
    out[0] = (float)(1.0 * l_loc + 0.5 * l_con + 0.3 * l_dist + 0.2 * l_smooth);
}

extern "C" void kernel_launch(void* const* d_in, const int* in_sizes, int n_in,
                              void* d_out, int out_size) {
    const float* scores = (const float*)d_in[0];
    const float* coords = (const float*)d_in[1];
    (void)in_sizes; (void)n_in; (void)out_size;

    // smem: max(staging 64KB, merge bufs (64*136 + 64*68) * 8B = 102KB)
    const int KNN_SMEM = (QPB * 136 + QPB * 68) * (int)sizeof(int2);
    cudaFuncSetAttribute(knn_kernel,
                         cudaFuncAttributeMaxDynamicSharedMemorySize, KNN_SMEM);

    zero_kernel<<<16, 1024>>>();
    rank_build_kernel<<<Nc / 256, 256>>>(scores);
    prefix_kernel<<<Bc, 1024>>>();
    knn_kernel<<<Bc * QBLKS, KTH, KNN_SMEM>>>(coords);
    loss_points_kernel<<<Nc / 256, 256>>>(scores, coords);
    finalize_kernel<<<1, 1>>>((float*)d_out);
}

// round 8
// speedup vs baseline: 2.6121x; 1.1202x over previous
#include <cuda_runtime.h>
#include <math.h>

#define Bc 2
#define Mc 8192
#define Nc (Bc * Mc)
#define KF 16
#define KN 8
#define NB 4096
#define BCAP 64

#define QPB 64                  // queries per block
#define SPLITS 8                // slice-threads per query
#define KTH (QPB * SPLITS)      // 512 threads
#define QBLKS (Mc / QPB)        // 128 per cloud; grid = 256
#define PASS_CANDS 4096         // candidates staged per pass (64KB)

// ---- scratch (device globals; no allocation allowed) ----
__device__ int    g_knn[(size_t)Nc * KF];
__device__ double g_acc[8];
__device__ int    g_hist[Bc][NB];
__device__ int    g_pref[Bc][NB];
__device__ int    g_members[Bc][NB * BCAP];

// ----- compare-exchange: a=min, b=max (2 ALU ops) -----
__device__ __forceinline__ void cx(unsigned& a, unsigned& b) {
    unsigned lo = min(a, b);
    b = max(a, b);
    a = lo;
}

// Green's optimal 60-comparator sorting network for n=16, ascending.
// Flat explicit pair list; in-place on k[0..15] (register-allocation-clean).
__device__ __forceinline__ void sort16(unsigned k[16]) {
    cx(k[0],k[1]); cx(k[2],k[3]); cx(k[4],k[5]); cx(k[6],k[7]);
    cx(k[8],k[9]); cx(k[10],k[11]); cx(k[12],k[13]); cx(k[14],k[15]);
    cx(k[0],k[2]); cx(k[4],k[6]); cx(k[8],k[10]); cx(k[12],k[14]);
    cx(k[1],k[3]); cx(k[5],k[7]); cx(k[9],k[11]); cx(k[13],k[15]);
    cx(k[0],k[4]); cx(k[8],k[12]); cx(k[1],k[5]); cx(k[9],k[13]);
    cx(k[2],k[6]); cx(k[10],k[14]); cx(k[3],k[7]); cx(k[11],k[15]);
    cx(k[0],k[8]); cx(k[1],k[9]); cx(k[2],k[10]); cx(k[3],k[11]);
    cx(k[4],k[12]); cx(k[5],k[13]); cx(k[6],k[14]); cx(k[7],k[15]);
    cx(k[5],k[10]); cx(k[6],k[9]); cx(k[3],k[12]); cx(k[13],k[14]);
    cx(k[7],k[11]); cx(k[1],k[2]); cx(k[4],k[8]);
    cx(k[1],k[4]); cx(k[7],k[13]); cx(k[2],k[8]); cx(k[11],k[14]);
    cx(k[2],k[4]); cx(k[5],k[6]); cx(k[9],k[10]); cx(k[11],k[13]);
    cx(k[3],k[8]); cx(k[7],k[12]);
    cx(k[6],k[8]); cx(k[10],k[12]); cx(k[3],k[5]); cx(k[7],k[9]);
    cx(k[3],k[4]); cx(k[5],k[6]); cx(k[7],k[8]); cx(k[9],k[10]);
    cx(k[11],k[12]);
    cx(k[6],k[7]); cx(k[8],k[9]);
}

// clean a bitonic 16-sequence -> ascending (32 CE)
__device__ __forceinline__ void clean16(unsigned k[16]) {
#pragma unroll
    for (int j = 8; j; j >>= 1)
#pragma unroll
        for (int i = 0; i < 16; ++i) {
            int l = i ^ j;
            if (l > i) cx(k[i], k[l]);
        }
}

// ================= kNN =================
// key = (float_bits(d) & 0x7FFFF800) | local_c(11 bits);  d = |c|^2-2q.c+|q|^2 >= -eps
// sign-clear maps the -eps boundary (self distance) to tiny positive: order-safe.
extern "C" __global__ void __launch_bounds__(KTH, 2)
knn_kernel(const float* __restrict__ coords) {
    extern __shared__ unsigned char sraw[];
    float4* sh = (float4*)sraw;

    const int tid = threadIdx.x;
    const int cloud = blockIdx.x >> 7;
    const int qblk = blockIdx.x & 127;
    const int qLocal = tid & (QPB - 1);
    const int split = tid >> 6;            // warp-uniform (64 threads per split)

    const float* cb = coords + (size_t)cloud * Mc * 3;
    const int q = qblk * QPB + qLocal;

    const float qx = cb[3 * q], qy = cb[3 * q + 1], qz = cb[3 * q + 2];
    const float qw = fmaf(qx, qx, fmaf(qy, qy, qz * qz));
    const float ax = -2.0f * qx, ay = -2.0f * qy, az = -2.0f * qz;

    unsigned tk[16];
#pragma unroll
    for (int t = 0; t < 16; ++t) tk[t] = 0xFFFFFFFFu;

#pragma unroll 1
    for (int pass = 0; pass < 2; ++pass) {
        __syncthreads();                         // previous consumers done
        const int wbase = pass * PASS_CANDS;
        for (int i = tid; i < PASS_CANDS; i += KTH) {
            const int jg = wbase + i;
            float x = cb[3 * jg], y = cb[3 * jg + 1], z = cb[3 * jg + 2];
            sh[i] = make_float4(x, y, z, fmaf(x, x, fmaf(y, y, z * z)));
        }
        __syncthreads();

        const float4* ps = sh + (split << 9);    // this thread's 512-slice
        const int cbase = pass << 9;             // local c base
#pragma unroll 1
        for (int b = 0; b < 512 / 16; ++b) {
            unsigned bk[16];
            const float4* p = ps + b * 16;
#pragma unroll
            for (int i = 0; i < 16; ++i) {
                float4 c = p[i];
                float d = fmaf(ax, c.x, fmaf(ay, c.y, fmaf(az, c.z, c.w + qw)));
                bk[i] = (__float_as_uint(d) & 0x7FFFF800u)
                      | (unsigned)(cbase + b * 16 + i);
            }
            sort16(bk);
#pragma unroll
            for (int i = 0; i < 16; ++i) tk[i] = min(tk[i], bk[15 - i]);
            clean16(tk);
        }
    }

    // ---- exact 8-way merge on (d21, global idx) via 3 pairwise rounds ----
    __syncthreads();
    int2* bufA = (int2*)sraw;                    // [QPB][136]: 8 segs x16 (+pad)
    int2* bufB = bufA + QPB * 136;               // [QPB][68] : 4 segs x16 (+pad)

#pragma unroll
    for (int t = 0; t < 16; ++t) {
        unsigned key = tk[t];
        int c = (int)(key & 0x7FFu);
        int g = ((c >> 9) << 12) + (split << 9) + (c & 511);
        bufA[qLocal * 136 + split * 16 + t] = make_int2((int)(key >> 11), g);
    }
    __syncthreads();

#define MERGE2(SRC, OFFA, OFFB, DSTSTMT)                                      \
    {                                                                         \
        int ii = 0, jj = 0;                                                   \
        _Pragma("unroll 1")                                                   \
        for (int r = 0; r < 16; ++r) {                                        \
            int2 a = (SRC)[(OFFA) + min(ii, 15)];                             \
            int2 b = (SRC)[(OFFB) + min(jj, 15)];                             \
            bool takeA = (jj >= 16) ||                                        \
                ((ii < 16) && (a.x < b.x || (a.x == b.x && a.y < b.y)));      \
            int2 o = takeA ? a : b;                                           \
            ii += takeA; jj += !takeA;                                        \
            DSTSTMT;                                                          \
        }                                                                     \
    }

    if (split < 4) {   // round 1: 8 -> 4
        const int ra = qLocal * 136 + split * 32;
        int2* dst = bufB + qLocal * 68 + split * 16;
        MERGE2(bufA, ra, ra + 16, dst[r] = o);
    }
    __syncthreads();
    if (split < 2) {   // round 2: 4 -> 2
        const int ra = qLocal * 68 + split * 32;
        int2* dst = bufA + qLocal * 136 + split * 16;
        MERGE2(bufB, ra, ra + 16, dst[r] = o);
    }
    __syncthreads();
    if (split == 0) {  // round 3: 2 -> 1, write result
        const int goff = cloud * Mc;
        int* out = g_knn + ((size_t)goff + q) * KF;
        const int ra = qLocal * 136;
        MERGE2(bufA, ra, ra + 16, out[r] = goff + o.y);
    }
}

// ================= rank bucketing (exact, replaces sort) =================
__global__ void zero_kernel() {
    const int t = blockIdx.x * blockDim.x + threadIdx.x;
    if (t < 8) g_acc[t] = 0.0;
    for (int i = t; i < Bc * NB; i += gridDim.x * blockDim.x)
        ((int*)g_hist)[i] = 0;
}

__global__ void rank_build_kernel(const float* __restrict__ scores) {
    const int i = blockIdx.x * blockDim.x + threadIdx.x;
    if (i >= Nc) return;
    const int cloud = i >> 13;
    const int local = i & (Mc - 1);
    const float s = scores[i];
    int b = (int)(s * (float)NB);
    b = b < 0 ? 0 : (b > NB - 1 ? NB - 1 : b);
    const int slot = atomicAdd(&g_hist[cloud][b], 1);
    if (slot < BCAP) g_members[cloud][b * BCAP + slot] = local;
}

__global__ void prefix_kernel() {
    __shared__ int sc[1024];
    const int cloud = blockIdx.x;
    const int t = threadIdx.x;
    const int base = t * 4;
    int h0 = g_hist[cloud][base + 0];
    int h1 = g_hist[cloud][base + 1];
    int h2 = g_hist[cloud][base + 2];
    int h3 = g_hist[cloud][base + 3];
    int sum = h0 + h1 + h2 + h3;
    sc[t] = sum;
    __syncthreads();
    for (int off = 1; off < 1024; off <<= 1) {
        int v = (t >= off) ? sc[t - off] : 0;
        __syncthreads();
        sc[t] += v;
        __syncthreads();
    }
    int excl = sc[t] - sum;
    g_pref[cloud][base + 0] = excl; excl += h0;
    g_pref[cloud][base + 1] = excl; excl += h1;
    g_pref[cloud][base + 2] = excl; excl += h2;
    g_pref[cloud][base + 3] = excl;
}

// ================= per-point losses (+ rank dist loss) =================
__global__ void loss_points_kernel(const float* __restrict__ scores,
                                   const float* __restrict__ coords) {
    const int i = blockIdx.x * blockDim.x + threadIdx.x;
    double acc[6] = {0, 0, 0, 0, 0, 0};

    {
        const float si = scores[i];
        const float xi = coords[3 * i], yi = coords[3 * i + 1], zi = coords[3 * i + 2];
        float nsum = 0.0f;
        const int* nb = g_knn + (size_t)i * KF;
#pragma unroll
        for (int r = 0; r < KF; ++r) {
            const int n = nb[r];
            const float sn = scores[n];
            const float sd = fabsf(si - sn);
            const float x = (1.0f - sd) * 2.0f;
            const float sig = 1.0f / (1.0f + expf(-x));
            if (r < KN) {
                const float dx = xi - coords[3 * n];
                const float dy = yi - coords[3 * n + 1];
                const float dz = zi - coords[3 * n + 2];
                const float dist = sqrtf(dx * dx + dy * dy + dz * dz);
                const float w = expf(-dist * 10.0f);
                acc[0] += (double)(w * sd * sd);
                acc[1] += (double)w;
                acc[2] += (double)logf(sig + 1e-8f);
                nsum += sn;
            } else {
                acc[3] += (double)logf(1.0f - sig + 1e-8f);
            }
        }
        const float dm = si - nsum * 0.125f;
        acc[4] = (double)(dm * dm);

        const int cloud = i >> 13;
        const int local = i & (Mc - 1);
        int b = (int)(si * (float)NB);
        b = b < 0 ? 0 : (b > NB - 1 ? NB - 1 : b);
        int cnt = g_hist[cloud][b];
        cnt = cnt > BCAP ? BCAP : cnt;
        int r = 0;
        const int* mem = &g_members[cloud][b * BCAP];
        for (int k = 0; k < cnt; ++k) {
            const int m = mem[k];
            const float sm = scores[(cloud << 13) + m];
            r += (sm < si) || (sm == si && m < local);
        }
        const int rank = g_pref[cloud][b] + r;
        const float df = si - (float)rank * (1.0f / (float)(Mc - 1));
        acc[5] = (double)(df * df);
    }

    const int lane = threadIdx.x & 31;
    const int wid = threadIdx.x >> 5;
#pragma unroll
    for (int k = 0; k < 6; ++k)
#pragma unroll
        for (int o = 16; o; o >>= 1)
            acc[k] += __shfl_down_sync(0xffffffffu, acc[k], o);

    __shared__ double red[8][6];
    if (lane == 0)
#pragma unroll
        for (int k = 0; k < 6; ++k) red[wid][k] = acc[k];
    __syncthreads();
    if (wid == 0 && lane < 6) {
        double s = 0.0;
#pragma unroll
        for (int w = 0; w < 8; ++w) s += red[w][lane];
        atomicAdd(&g_acc[lane], s);
    }
}

// ================= finalize =================
__global__ void finalize_kernel(float* out) {
    const double l_loc = g_acc[0] / fmax(g_acc[1], 1e-8);
    const double l_pos = -g_acc[2] / (double)((size_t)Nc * KN);
    const double l_neg = -g_acc[3] / (double)((size_t)Nc * KN);
    const double l_con = l_pos + l_neg;
    const double l_smooth = g_acc[4] / (double)Nc;
    const double l_dist = g_acc[5] / (double)Nc;
    out[0] = (float)(1.0 * l_loc + 0.5 * l_con + 0.3 * l_dist + 0.2 * l_smooth);
}

extern "C" void kernel_launch(void* const* d_in, const int* in_sizes, int n_in,
                              void* d_out, int out_size) {
    const float* scores = (const float*)d_in[0];
    const float* coords = (const float*)d_in[1];
    (void)in_sizes; (void)n_in; (void)out_size;

    const int KNN_SMEM = (QPB * 136 + QPB * 68) * (int)sizeof(int2);
    cudaFuncSetAttribute(knn_kernel,
                         cudaFuncAttributeMaxDynamicSharedMemorySize, KNN_SMEM);

    zero_kernel<<<16, 1024>>>();
    rank_build_kernel<<<Nc / 256, 256>>>(scores);
    prefix_kernel<<<Bc, 1024>>>();
    knn_kernel<<<Bc * QBLKS, KTH, KNN_SMEM>>>(coords);
    loss_points_kernel<<<Nc / 256, 256>>>(scores, coords);
    finalize_kernel<<<1, 1>>>((float*)d_out);
}